// round 10
// baseline (speedup 1.0000x reference)
#include <cuda_runtime.h>

// Pair_83811991814342: out[i*512+j] = concat(x[i], x[j], inter/area_i, inter/area_j)
// n = 512, d = 260, rows of 522 floats. HBM-write-bound (547 MB stores,
// pinned at 6.36 TB/s across R6/R7).
//
// R9 = R7 store engine, ONE lever: TI 4 -> 2 (4096 blocks, ~6.9 waves vs 3.46)
// to eliminate wave-tail quantization (last wave only 272/592 slots filled at
// TI=4 -> >half the SMs idle for the final quarter of the run). Warp map:
// warp = (il in {0,1}) x (jh in {0..3}), 8 rows/warp; store body unchanged.

#define DD      260
#define ROWLEN  522          // 2*D + 2 floats per output row
#define TI      2
#define TJ      32
#define NTHREADS 256

__global__ __launch_bounds__(NTHREADS, 4)
void pair_kernel(const float* __restrict__ in, float* __restrict__ out, int n)
{
    __shared__ float  xi[TI][DD];
    __shared__ float  xj[TJ][DD];
    __shared__ float2 r12[TI][TJ];

    const int tid = threadIdx.x;
    const int i0  = blockIdx.y * TI;
    const int j0  = blockIdx.x * TJ;

    // ---- Phase 1: cooperative float4 copy of tiles into SMEM ----
    {
        const float4* gi = (const float4*)(in + (size_t)i0 * DD);
        float4*       si = (float4*)&xi[0][0];
        #pragma unroll
        for (int t = tid; t < TI * DD / 4; t += NTHREADS) si[t] = gi[t];

        const float4* gj = (const float4*)(in + (size_t)j0 * DD);
        float4*       sj = (float4*)&xj[0][0];
        for (int t = tid; t < TJ * DD / 4; t += NTHREADS) sj[t] = gj[t];
    }
    __syncthreads();

    // ---- Phase 2: precompute (r1, r2) for all TI x TJ pairs ----
    if (tid < TI * TJ) {
        const int ii = tid / TJ;
        const int jj = tid % TJ;
        const float x1i = xi[ii][256], y1i = xi[ii][257];
        const float x2i = xi[ii][258], y2i = xi[ii][259];
        const float x1j = xj[jj][256], y1j = xj[jj][257];
        const float x2j = xj[jj][258], y2j = xj[jj][259];
        const float ai = (x2i - x1i) * (y2i - y1i);
        const float aj = (x2j - x1j) * (y2j - y1j);
        const float w  = fmaxf(0.0f, fminf(x2i, x2j) - fmaxf(x1i, x1j));
        const float h  = fmaxf(0.0f, fminf(y2i, y2j) - fmaxf(y1i, y1j));
        const float inter = w * h;
        r12[ii][jj] = make_float2(inter / ai, inter / aj);
    }
    __syncthreads();

    // ---- Phase 3: warp-per-(i, 8-j-strip), wide aligned stores ----
    const int wrp  = tid >> 5;
    const int lane = tid & 31;
    const int il   = wrp >> 2;        // 0..1  (local i)
    const int jh   = wrp & 3;         // 0..3  (j quarter: 8 rows each)

    const float4* xi4 = (const float4*)&xi[il][0];   // il*1040 B, 16B aligned
    const float2* xi2 = (const float2*)&xi[il][0];

    // Row-invariant hoists.
    const float4 w0  = xi4[lane];          // floats 4*lane   .. +3
    const float4 w1  = xi4[lane + 32];     // floats 128+4*lane .. +3
    const float4 x64 = xi4[64];            // floats 256..259 (broadcast)

    const int jbase = jh * 8;
    #pragma unroll 4
    for (int r = 0; r < 8; ++r) {
        const int jj = jbase + r;
        const int j  = j0 + jj;
        const size_t R = ((size_t)(i0 + il) * (size_t)n + (size_t)j) * (size_t)ROWLEN;
        const float2* xj2 = (const float2*)&xj[jj][0];   // jj*1040 B, 16B aligned
        const float4* xj4 = (const float4*)&xj[jj][0];
        const float2  rr  = r12[il][jj];

        if ((j & 1) == 0) {
            // ---- even row: R % 4 == 0, float4-aligned from float 0 ----
            float4* o4 = (float4*)(out + R);
            __stcs(&o4[lane     ], w0);                       // floats 0..127
            __stcs(&o4[lane + 32], w1);                       // floats 128..255
            {   // q = 64 + lane: q==64 -> xi floats 256..259, else xj4[q-65]
                const float4 b = xj4[lane ? (lane - 1) : 0];
                __stcs(&o4[lane + 64], lane ? b : x64);
            }
            __stcs(&o4[lane + 96], xj4[lane + 31]);           // floats 384..511
            if (lane < 2)
                __stcs(&o4[lane + 128], xj4[lane + 63]);      // floats 512..519
            if (lane == 2)
                __stcs((float2*)(out + R) + 260, rr);         // floats 520,521
        } else {
            // ---- odd row: leading float2, then float4-aligned at R+2 ----
            float2* o2 = (float2*)(out + R);
            float4* o4 = (float4*)(out + R + 2);
            if (lane == 0) __stcs(&o2[0], xi2[0]);            // floats 0,1
            {   // q = lane: floats 2+4q -> xi2[1+2q], xi2[2+2q]
                const float2 a0 = xi2[1 + 2*lane], a1 = xi2[2 + 2*lane];
                __stcs(&o4[lane], make_float4(a0.x, a0.y, a1.x, a1.y));
            }
            {   // q = 32+lane
                const float2 b0 = xi2[65 + 2*lane], b1 = xi2[66 + 2*lane];
                __stcs(&o4[lane + 32], make_float4(b0.x, b0.y, b1.x, b1.y));
            }
            {   // q = 64+lane: lane 0 straddles xi->xj
                const float2 c0 = lane ? xj2[2*lane - 1] : xi2[129];
                const float2 c1 = xj2[2*lane];
                __stcs(&o4[lane + 64], make_float4(c0.x, c0.y, c1.x, c1.y));
            }
            {   // q = 96+lane
                const float2 d0 = xj2[63 + 2*lane], d1 = xj2[64 + 2*lane];
                __stcs(&o4[lane + 96], make_float4(d0.x, d0.y, d1.x, d1.y));
            }
            if (lane == 0) {                                  // q = 128
                const float2 e0 = xj2[127], e1 = xj2[128];
                __stcs(&o4[128], make_float4(e0.x, e0.y, e1.x, e1.y));
            }
            if (lane == 1) {                                  // q = 129 (xj tail + r12)
                const float2 f0 = xj2[129];
                __stcs(&o4[129], make_float4(f0.x, f0.y, rr.x, rr.y));
            }
        }
    }
}

extern "C" void kernel_launch(void* const* d_in, const int* in_sizes, int n_in,
                              void* d_out, int out_size)
{
    const float* in  = (const float*)d_in[0];
    float*       out = (float*)d_out;

    // inputs: (1, 2n, D) fp32 ; n = 512 for this problem
    const int n = (in_sizes[0] / DD) / 2;

    dim3 grid(n / TJ, n / TI);   // (16, 256) = 4096 blocks
    pair_kernel<<<grid, NTHREADS>>>(in, out, n);
}

// round 11
// speedup vs baseline: 1.0082x; 1.0082x over previous
#include <cuda_runtime.h>

// Pair_83811991814342: out[i*512+j] = concat(x[i], x[j], inter/area_i, inter/area_j)
// n = 512, d = 260, rows of 522 floats. HBM-write-bound: R6/R7/R9 (three
// different structures) all pinned at 6.36-6.37 TB/s sustained writes ->
// treating that as the DRAM write ceiling.
//
// R11 = R7 (best, 86.0us: TI=4 x TJ=32, wide aligned STG.128 + .cs) with ONE
// lever: fully unroll the 16-row store loop to deepen per-warp store
// issue-ahead (more outstanding STGs -> deeper DRAM write queue).

#define DD      260
#define ROWLEN  522          // 2*D + 2 floats per output row
#define TI      4
#define TJ      32
#define NTHREADS 256

__global__ __launch_bounds__(NTHREADS, 4)
void pair_kernel(const float* __restrict__ in, float* __restrict__ out, int n)
{
    __shared__ float  xi[TI][DD];
    __shared__ float  xj[TJ][DD];
    __shared__ float2 r12[TI][TJ];

    const int tid = threadIdx.x;
    const int i0  = blockIdx.y * TI;
    const int j0  = blockIdx.x * TJ;

    // ---- Phase 1: cooperative float4 copy of tiles into SMEM ----
    {
        const float4* gi = (const float4*)(in + (size_t)i0 * DD);
        float4*       si = (float4*)&xi[0][0];
        #pragma unroll
        for (int t = tid; t < TI * DD / 4; t += NTHREADS) si[t] = gi[t];

        const float4* gj = (const float4*)(in + (size_t)j0 * DD);
        float4*       sj = (float4*)&xj[0][0];
        for (int t = tid; t < TJ * DD / 4; t += NTHREADS) sj[t] = gj[t];
    }
    __syncthreads();

    // ---- Phase 2: precompute (r1, r2) for all TI x TJ pairs ----
    if (tid < TI * TJ) {
        const int ii = tid / TJ;
        const int jj = tid % TJ;
        const float x1i = xi[ii][256], y1i = xi[ii][257];
        const float x2i = xi[ii][258], y2i = xi[ii][259];
        const float x1j = xj[jj][256], y1j = xj[jj][257];
        const float x2j = xj[jj][258], y2j = xj[jj][259];
        const float ai = (x2i - x1i) * (y2i - y1i);
        const float aj = (x2j - x1j) * (y2j - y1j);
        const float w  = fmaxf(0.0f, fminf(x2i, x2j) - fmaxf(x1i, x1j));
        const float h  = fmaxf(0.0f, fminf(y2i, y2j) - fmaxf(y1i, y1j));
        const float inter = w * h;
        r12[ii][jj] = make_float2(inter / ai, inter / aj);
    }
    __syncthreads();

    // ---- Phase 3: warp-per-row, wide aligned stores ----
    const int wrp  = tid >> 5;
    const int lane = tid & 31;
    const int il   = wrp >> 1;        // 0..3  (local i)
    const int jh   = wrp & 1;         // 0/1   (j half: 16 rows each)

    const float4* xi4 = (const float4*)&xi[il][0];   // il*1040 B, 16B aligned
    const float2* xi2 = (const float2*)&xi[il][0];

    // Row-invariant hoists.
    const float4 w0  = xi4[lane];          // floats 4*lane   .. +3
    const float4 w1  = xi4[lane + 32];     // floats 128+4*lane .. +3
    const float4 x64 = xi4[64];            // floats 256..259 (broadcast)

    const int jbase = jh * 16;
    #pragma unroll
    for (int r = 0; r < 16; ++r) {
        const int jj = jbase + r;
        const int j  = j0 + jj;
        const size_t R = ((size_t)(i0 + il) * (size_t)n + (size_t)j) * (size_t)ROWLEN;
        const float2* xj2 = (const float2*)&xj[jj][0];   // jj*1040 B, 16B aligned
        const float4* xj4 = (const float4*)&xj[jj][0];
        const float2  rr  = r12[il][jj];

        if ((j & 1) == 0) {
            // ---- even row: R % 4 == 0, float4-aligned from float 0 ----
            float4* o4 = (float4*)(out + R);
            __stcs(&o4[lane     ], w0);                       // floats 0..127
            __stcs(&o4[lane + 32], w1);                       // floats 128..255
            {   // q = 64 + lane: q==64 -> xi floats 256..259, else xj4[q-65]
                const float4 b = xj4[lane ? (lane - 1) : 0];
                __stcs(&o4[lane + 64], lane ? b : x64);
            }
            __stcs(&o4[lane + 96], xj4[lane + 31]);           // floats 384..511
            if (lane < 2)
                __stcs(&o4[lane + 128], xj4[lane + 63]);      // floats 512..519
            if (lane == 2)
                __stcs((float2*)(out + R) + 260, rr);         // floats 520,521
        } else {
            // ---- odd row: leading float2, then float4-aligned at R+2 ----
            float2* o2 = (float2*)(out + R);
            float4* o4 = (float4*)(out + R + 2);
            if (lane == 0) __stcs(&o2[0], xi2[0]);            // floats 0,1
            {   // q = lane: floats 2+4q -> xi2[1+2q], xi2[2+2q]
                const float2 a0 = xi2[1 + 2*lane], a1 = xi2[2 + 2*lane];
                __stcs(&o4[lane], make_float4(a0.x, a0.y, a1.x, a1.y));
            }
            {   // q = 32+lane
                const float2 b0 = xi2[65 + 2*lane], b1 = xi2[66 + 2*lane];
                __stcs(&o4[lane + 32], make_float4(b0.x, b0.y, b1.x, b1.y));
            }
            {   // q = 64+lane: lane 0 straddles xi->xj
                const float2 c0 = lane ? xj2[2*lane - 1] : xi2[129];
                const float2 c1 = xj2[2*lane];
                __stcs(&o4[lane + 64], make_float4(c0.x, c0.y, c1.x, c1.y));
            }
            {   // q = 96+lane
                const float2 d0 = xj2[63 + 2*lane], d1 = xj2[64 + 2*lane];
                __stcs(&o4[lane + 96], make_float4(d0.x, d0.y, d1.x, d1.y));
            }
            if (lane == 0) {                                  // q = 128
                const float2 e0 = xj2[127], e1 = xj2[128];
                __stcs(&o4[128], make_float4(e0.x, e0.y, e1.x, e1.y));
            }
            if (lane == 1) {                                  // q = 129 (xj tail + r12)
                const float2 f0 = xj2[129];
                __stcs(&o4[129], make_float4(f0.x, f0.y, rr.x, rr.y));
            }
        }
    }
}

extern "C" void kernel_launch(void* const* d_in, const int* in_sizes, int n_in,
                              void* d_out, int out_size)
{
    const float* in  = (const float*)d_in[0];
    float*       out = (float*)d_out;

    // inputs: (1, 2n, D) fp32 ; n = 512 for this problem
    const int n = (in_sizes[0] / DD) / 2;

    dim3 grid(n / TJ, n / TI);   // (16, 128) = 2048 blocks
    pair_kernel<<<grid, NTHREADS>>>(in, out, n);
}